// round 9
// baseline (speedup 1.0000x reference)
#include <cuda_runtime.h>
#include <cuda_bf16.h>
#include <math.h>
#include <stdint.h>

#define S_LEN 2048
#define DIM 2048
#define NH 32
#define NKV 8
#define HD 64
#define KVDIM (NKV * HD)   // 512

// ---------------------------------------------------------------------------
// Scratch (bf16 hi/lo pairs stored as uint16)
// ---------------------------------------------------------------------------
__device__ float g_q[S_LEN * DIM];     // fp32 pre-rope q
__device__ float g_k[S_LEN * KVDIM];   // fp32 pre-rope k
__device__ __align__(16) uint16_t g_xh[S_LEN * DIM],  g_xl[S_LEN * DIM];
__device__ __align__(16) uint16_t g_wqh[DIM * DIM],   g_wql[DIM * DIM];
__device__ __align__(16) uint16_t g_wkh[KVDIM * DIM], g_wkl[KVDIM * DIM];
__device__ __align__(16) uint16_t g_wvh[KVDIM * DIM], g_wvl[KVDIM * DIM];
__device__ __align__(16) uint16_t g_woh[DIM * DIM],   g_wol[DIM * DIM];
__device__ __align__(16) uint16_t g_qh[S_LEN * DIM],  g_ql[S_LEN * DIM];
__device__ __align__(16) uint16_t g_kh[S_LEN * KVDIM], g_kl[S_LEN * KVDIM];
__device__ __align__(16) uint16_t g_vh[S_LEN * KVDIM], g_vl[S_LEN * KVDIM];
__device__ __align__(16) uint16_t g_aoh[S_LEN * DIM], g_aol[S_LEN * DIM];
__device__ float g_ct[S_LEN * 32];
__device__ float g_st[S_LEN * 32];

// ---------------------------------------------------------------------------
// helpers
// ---------------------------------------------------------------------------
__device__ __forceinline__ uint32_t smem_u32(const void* p) {
    uint32_t a;
    asm("{ .reg .u64 t; cvta.to.shared.u64 t, %1; cvt.u32.u64 %0, t; }"
        : "=r"(a) : "l"(p));
    return a;
}
__device__ __forceinline__ void ldm_x4(uint32_t* r, uint32_t addr) {
    asm volatile("ldmatrix.sync.aligned.m8n8.x4.shared.b16 {%0,%1,%2,%3}, [%4];"
                 : "=r"(r[0]), "=r"(r[1]), "=r"(r[2]), "=r"(r[3]) : "r"(addr));
}
__device__ __forceinline__ void ldm_x4_t(uint32_t* r, uint32_t addr) {
    asm volatile("ldmatrix.sync.aligned.m8n8.x4.trans.shared.b16 {%0,%1,%2,%3}, [%4];"
                 : "=r"(r[0]), "=r"(r[1]), "=r"(r[2]), "=r"(r[3]) : "r"(addr));
}
__device__ __forceinline__ void mma_bf16(float* d, const uint32_t* a,
                                         const uint32_t* b) {
    asm volatile(
        "mma.sync.aligned.m16n8k16.row.col.f32.bf16.bf16.f32 "
        "{%0,%1,%2,%3}, {%4,%5,%6,%7}, {%8,%9}, {%0,%1,%2,%3};"
        : "+f"(d[0]), "+f"(d[1]), "+f"(d[2]), "+f"(d[3])
        : "r"(a[0]), "r"(a[1]), "r"(a[2]), "r"(a[3]), "r"(b[0]), "r"(b[1]));
}
__device__ __forceinline__ uint32_t pack_bf16(float x, float y) {
    __nv_bfloat162 t = __float22bfloat162_rn(make_float2(x, y));
    return *reinterpret_cast<uint32_t*>(&t);
}
__device__ __forceinline__ void split2(float x, float y, uint32_t& hi, uint32_t& lo) {
    __nv_bfloat162 h = __float22bfloat162_rn(make_float2(x, y));
    hi = *reinterpret_cast<uint32_t*>(&h);
    __nv_bfloat162 l = __float22bfloat162_rn(make_float2(
        x - __bfloat162float(h.x), y - __bfloat162float(h.y)));
    lo = *reinterpret_cast<uint32_t*>(&l);
}

#define CP_ASYNC16(dst_u32, gsrc) \
    asm volatile("cp.async.cg.shared.global [%0], [%1], 16;" \
                 :: "r"(dst_u32), "l"(gsrc) : "memory")
#define CP_COMMIT() asm volatile("cp.async.commit_group;" ::: "memory")
#define CP_WAIT(n)  asm volatile("cp.async.wait_group %0;" :: "n"(n) : "memory")

// ---------------------------------------------------------------------------
// fp32 -> bf16 hi/lo split (elementwise)
// ---------------------------------------------------------------------------
__global__ __launch_bounds__(256)
void conv_split(const float4* __restrict__ src, uint2* __restrict__ hi,
                uint2* __restrict__ lo, int n4) {
    int i = blockIdx.x * 256 + threadIdx.x;
    if (i >= n4) return;
    float4 f = src[i];
    uint2 h, l;
    split2(f.x, f.y, h.x, l.x);
    split2(f.z, f.w, h.y, l.y);
    hi[i] = h;
    lo[i] = l;
}

// ---------------------------------------------------------------------------
// Tensor-core GEMM, bf16 hi/lo inputs, cp.async 2-stage pipeline.
// C[M,N] = (Ah+Al)[M,K] @ (Bh+Bl)[N,K]^T  (bf16x3). fp32 or bf16-split output.
// CTA 128x128, BK=32, 256 threads (8 warps 4x2), warp tile 32x64.
// ---------------------------------------------------------------------------
#define GPAD 40
#define GSZ (128 * GPAD)   // elements per array per stage

__global__ __launch_bounds__(256)
void mma_gemm_bf16(const uint16_t* __restrict__ Ah, const uint16_t* __restrict__ Al,
                   const uint16_t* __restrict__ Bh, const uint16_t* __restrict__ Bl,
                   float* __restrict__ C, uint16_t* __restrict__ Ch,
                   uint16_t* __restrict__ Cl, int M, int N, int K) {
    extern __shared__ uint16_t dsm[];   // [8][GSZ]: Ah0,Ah1,Al0,Al1,Bh0,Bh1,Bl0,Bl1
    const uint32_t sb = smem_u32(dsm);

    const int tid  = threadIdx.x;
    const int wid  = tid >> 5;
    const int lane = tid & 31;
    const int wm = (wid & 3) * 32;
    const int wn = (wid >> 2) * 64;
    const int m0 = blockIdx.y * 128;
    const int n0 = blockIdx.x * 128;

    float acc[2][8][4];
#pragma unroll
    for (int i = 0; i < 2; i++)
#pragma unroll
        for (int j = 0; j < 8; j++)
#pragma unroll
            for (int e = 0; e < 4; e++) acc[i][j][e] = 0.f;

    const int a_r = lane & 15;
    const int a_c = (lane >> 4) << 3;
    const int b_r = (lane & 7) + ((lane >> 4) << 3);
    const int b_c = ((lane >> 3) & 1) << 3;

    // chunk copy: per array 512 16B-chunks (128 rows x 4), 2 per thread
    auto load_chunk = [&](int k0, int stage) {
#pragma unroll
        for (int i = 0; i < 2; i++) {
            int cid = tid + i * 256;
            int r = cid >> 2;
            int c = (cid & 3) * 8;
            uint32_t soff = (uint32_t)(r * GPAD + c) * 2;
            const uint16_t* gAh = Ah + (size_t)(m0 + r) * K + k0 + c;
            const uint16_t* gAl = Al + (size_t)(m0 + r) * K + k0 + c;
            const uint16_t* gBh = Bh + (size_t)(n0 + r) * K + k0 + c;
            const uint16_t* gBl = Bl + (size_t)(n0 + r) * K + k0 + c;
            CP_ASYNC16(sb + (uint32_t)(0 + stage) * GSZ * 2 + soff, gAh);
            CP_ASYNC16(sb + (uint32_t)(2 + stage) * GSZ * 2 + soff, gAl);
            CP_ASYNC16(sb + (uint32_t)(4 + stage) * GSZ * 2 + soff, gBh);
            CP_ASYNC16(sb + (uint32_t)(6 + stage) * GSZ * 2 + soff, gBl);
        }
    };

    const int nk = K / 32;
    load_chunk(0, 0);
    CP_COMMIT();

    for (int ck = 0; ck < nk; ck++) {
        const int cur = ck & 1;
        if (ck + 1 < nk) {
            load_chunk((ck + 1) * 32, (ck + 1) & 1);
            CP_COMMIT();
            CP_WAIT(1);
        } else {
            CP_WAIT(0);
        }
        __syncthreads();

        const uint32_t bAh = sb + (uint32_t)(0 + cur) * GSZ * 2;
        const uint32_t bAl = sb + (uint32_t)(2 + cur) * GSZ * 2;
        const uint32_t bBh = sb + (uint32_t)(4 + cur) * GSZ * 2;
        const uint32_t bBl = sb + (uint32_t)(6 + cur) * GSZ * 2;

#pragma unroll
        for (int ks = 0; ks < 2; ks++) {
            const int kc = ks * 16;
            uint32_t ah[2][4], al[2][4];
#pragma unroll
            for (int mi = 0; mi < 2; mi++) {
                uint32_t off = (uint32_t)((wm + mi * 16 + a_r) * GPAD + kc + a_c) * 2;
                ldm_x4(ah[mi], bAh + off);
                ldm_x4(al[mi], bAl + off);
            }
            uint32_t bh[8][2], bl[8][2];
#pragma unroll
            for (int nj = 0; nj < 4; nj++) {
                uint32_t off = (uint32_t)((wn + nj * 16 + b_r) * GPAD + kc + b_c) * 2;
                uint32_t t[4];
                ldm_x4(t, bBh + off);
                bh[nj * 2][0] = t[0]; bh[nj * 2][1] = t[1];
                bh[nj * 2 + 1][0] = t[2]; bh[nj * 2 + 1][1] = t[3];
                ldm_x4(t, bBl + off);
                bl[nj * 2][0] = t[0]; bl[nj * 2][1] = t[1];
                bl[nj * 2 + 1][0] = t[2]; bl[nj * 2 + 1][1] = t[3];
            }
#pragma unroll
            for (int mi = 0; mi < 2; mi++)
#pragma unroll
                for (int ni = 0; ni < 8; ni++) {
                    mma_bf16(acc[mi][ni], ah[mi], bh[ni]);
                    mma_bf16(acc[mi][ni], ah[mi], bl[ni]);
                    mma_bf16(acc[mi][ni], al[mi], bh[ni]);
                }
        }
        __syncthreads();
    }

    const int g = lane >> 2, t = lane & 3;
    if (C != nullptr) {
#pragma unroll
        for (int mi = 0; mi < 2; mi++) {
            int r0 = m0 + wm + mi * 16 + g;
#pragma unroll
            for (int ni = 0; ni < 8; ni++) {
                int c = n0 + wn + ni * 8 + t * 2;
                *reinterpret_cast<float2*>(C + (size_t)r0 * N + c) =
                    make_float2(acc[mi][ni][0], acc[mi][ni][1]);
                *reinterpret_cast<float2*>(C + (size_t)(r0 + 8) * N + c) =
                    make_float2(acc[mi][ni][2], acc[mi][ni][3]);
            }
        }
    } else {
#pragma unroll
        for (int mi = 0; mi < 2; mi++) {
            int r0 = m0 + wm + mi * 16 + g;
#pragma unroll
            for (int ni = 0; ni < 8; ni++) {
                int c = n0 + wn + ni * 8 + t * 2;
                uint32_t h0, l0, h1, l1;
                split2(acc[mi][ni][0], acc[mi][ni][1], h0, l0);
                split2(acc[mi][ni][2], acc[mi][ni][3], h1, l1);
                *reinterpret_cast<uint32_t*>(Ch + (size_t)r0 * N + c) = h0;
                *reinterpret_cast<uint32_t*>(Cl + (size_t)r0 * N + c) = l0;
                *reinterpret_cast<uint32_t*>(Ch + (size_t)(r0 + 8) * N + c) = h1;
                *reinterpret_cast<uint32_t*>(Cl + (size_t)(r0 + 8) * N + c) = l1;
            }
        }
    }
}

// ---------------------------------------------------------------------------
// RoPE: table (verified), then apply + scale(q) + bf16 split.
// ---------------------------------------------------------------------------
__global__ void rope_table_kernel() {
    int s = blockIdx.x;
    int i = threadIdx.x;
    float e = (float)i / 32.0f;
    float fr = 1.0f / powf(10000.0f, e);
    float angf = (float)s * fr;
    double ang = (double)angf;
    g_ct[s * 32 + i] = (float)cos(ang);
    g_st[s * 32 + i] = (float)sin(ang);
}

__global__ __launch_bounds__(256)
void rope_split_kernel() {
    const int s = blockIdx.x;
    for (int item = threadIdx.x; item < (NH + NKV) * 32; item += 256) {
        float c, sn;
        int i;
        if (item < NH * 32) {
            int h = item >> 5; i = item & 31;
            c = g_ct[s * 32 + i]; sn = g_st[s * 32 + i];
            size_t base = (size_t)s * DIM + h * HD;
            float x1 = g_q[base + i], x2 = g_q[base + i + 32];
            float r1 = (x1 * c - x2 * sn) * 0.125f;
            float r2 = (x2 * c + x1 * sn) * 0.125f;
            __nv_bfloat16 h1 = __float2bfloat16_rn(r1);
            __nv_bfloat16 h2 = __float2bfloat16_rn(r2);
            g_qh[base + i]      = *reinterpret_cast<uint16_t*>(&h1);
            g_qh[base + i + 32] = *reinterpret_cast<uint16_t*>(&h2);
            __nv_bfloat16 l1 = __float2bfloat16_rn(r1 - __bfloat162float(h1));
            __nv_bfloat16 l2 = __float2bfloat16_rn(r2 - __bfloat162float(h2));
            g_ql[base + i]      = *reinterpret_cast<uint16_t*>(&l1);
            g_ql[base + i + 32] = *reinterpret_cast<uint16_t*>(&l2);
        } else {
            int it = item - NH * 32;
            int h = it >> 5; i = it & 31;
            c = g_ct[s * 32 + i]; sn = g_st[s * 32 + i];
            size_t base = (size_t)s * KVDIM + h * HD;
            float x1 = g_k[base + i], x2 = g_k[base + i + 32];
            float r1 = x1 * c - x2 * sn;
            float r2 = x2 * c + x1 * sn;
            __nv_bfloat16 h1 = __float2bfloat16_rn(r1);
            __nv_bfloat16 h2 = __float2bfloat16_rn(r2);
            g_kh[base + i]      = *reinterpret_cast<uint16_t*>(&h1);
            g_kh[base + i + 32] = *reinterpret_cast<uint16_t*>(&h2);
            __nv_bfloat16 l1 = __float2bfloat16_rn(r1 - __bfloat162float(h1));
            __nv_bfloat16 l2 = __float2bfloat16_rn(r2 - __bfloat162float(h2));
            g_kl[base + i]      = *reinterpret_cast<uint16_t*>(&l1);
            g_kl[base + i + 32] = *reinterpret_cast<uint16_t*>(&l2);
        }
    }
}

// ---------------------------------------------------------------------------
// Tensor-core flash attention on pre-split bf16 inputs; bf16-split output.
// Grid (32 qtiles, 32 heads), 128 threads (4 warps), 64x64 tiles.
// ---------------------------------------------------------------------------
#define KPAD 72
#define LOG2E 1.4426950408889634f

__global__ __launch_bounds__(128)
void attn_tc_kernel() {
    __shared__ __align__(16) uint16_t sKh[64][KPAD];
    __shared__ __align__(16) uint16_t sKl[64][KPAD];
    __shared__ __align__(16) uint16_t sVh[64][KPAD];
    __shared__ __align__(16) uint16_t sVl[64][KPAD];

    const int qt = (int)gridDim.x - 1 - (int)blockIdx.x;
    const int h  = blockIdx.y;
    const int kvh = h >> 2;
    const int tid = threadIdx.x;
    const int wid = tid >> 5;
    const int lane = tid & 31;
    const int g = lane >> 2;
    const int t = lane & 3;

    const uint32_t bKh = smem_u32(sKh), bKl = smem_u32(sKl);
    const uint32_t bVh = smem_u32(sVh), bVl = smem_u32(sVl);

    // ---- stage Q (pre-scaled, pre-split) and pull fragments ----
#pragma unroll
    for (int it = 0; it < 4; it++) {
        int cid = tid + it * 128;          // 512 chunks of 8 bf16
        int r = cid >> 3;
        int c = (cid & 7) * 8;
        *reinterpret_cast<uint4*>(&sKh[r][c]) = *reinterpret_cast<const uint4*>(
            g_qh + (size_t)(qt * 64 + r) * DIM + h * HD + c);
        *reinterpret_cast<uint4*>(&sKl[r][c]) = *reinterpret_cast<const uint4*>(
            g_ql + (size_t)(qt * 64 + r) * DIM + h * HD + c);
    }
    __syncthreads();

    uint32_t qh[4][4], ql[4][4];
    {
        int row = wid * 16 + (lane & 15);
        int col = ((lane >> 4) & 1) * 8;
#pragma unroll
        for (int c = 0; c < 4; c++) {
            uint32_t off = (uint32_t)(row * KPAD + c * 16 + col) * 2;
            ldm_x4(qh[c], bKh + off);
            ldm_x4(ql[c], bKl + off);
        }
    }
    __syncthreads();

    float mr[2] = {-INFINITY, -INFINITY};
    float lr[2] = {0.f, 0.f};
    float D[8][4];
#pragma unroll
    for (int i = 0; i < 8; i++)
#pragma unroll
        for (int j = 0; j < 4; j++) D[i][j] = 0.f;

    const int kb_row = (lane & 7) + ((lane >> 4) << 3);
    const int kb_col = ((lane >> 3) & 1) * 8;
    const int vb_row = (lane & 7) + (((lane >> 3) & 1) << 3);
    const int vb_col = ((lane >> 4) & 1) * 8;

    for (int kt = 0; kt <= qt; kt++) {
        // ---- stage K/V (pre-split) ----
#pragma unroll
        for (int it = 0; it < 4; it++) {
            int cid = tid + it * 128;
            int r = cid >> 3;
            int c = (cid & 7) * 8;
            size_t off = (size_t)(kt * 64 + r) * KVDIM + kvh * HD + c;
            *reinterpret_cast<uint4*>(&sKh[r][c]) =
                *reinterpret_cast<const uint4*>(g_kh + off);
            *reinterpret_cast<uint4*>(&sKl[r][c]) =
                *reinterpret_cast<const uint4*>(g_kl + off);
            *reinterpret_cast<uint4*>(&sVh[r][c]) =
                *reinterpret_cast<const uint4*>(g_vh + off);
            *reinterpret_cast<uint4*>(&sVl[r][c]) =
                *reinterpret_cast<const uint4*>(g_vl + off);
        }
        __syncthreads();

        // ---- S = Q K^T (bf16x3) ----
        float S[8][4];
#pragma unroll
        for (int i = 0; i < 8; i++)
#pragma unroll
            for (int j = 0; j < 4; j++) S[i][j] = 0.f;

#pragma unroll
        for (int c = 0; c < 4; c++) {
#pragma unroll
            for (int nbp = 0; nbp < 4; nbp++) {
                uint32_t kh[4], kl[4];
                uint32_t off = (uint32_t)((nbp * 16 + kb_row) * KPAD + c * 16 + kb_col) * 2;
                ldm_x4(kh, bKh + off);
                ldm_x4(kl, bKl + off);
                mma_bf16(S[2 * nbp],     qh[c], kh);
                mma_bf16(S[2 * nbp],     qh[c], kl);
                mma_bf16(S[2 * nbp],     ql[c], kh);
                mma_bf16(S[2 * nbp + 1], qh[c], kh + 2);
                mma_bf16(S[2 * nbp + 1], qh[c], kl + 2);
                mma_bf16(S[2 * nbp + 1], ql[c], kh + 2);
            }
        }

        if (kt == qt) {
            int r0 = wid * 16 + g;
#pragma unroll
            for (int nb = 0; nb < 8; nb++) {
                int c0 = nb * 8 + 2 * t;
                if (c0 > r0)     S[nb][0] = -INFINITY;
                if (c0 + 1 > r0) S[nb][1] = -INFINITY;
                if (c0 > r0 + 8)     S[nb][2] = -INFINITY;
                if (c0 + 1 > r0 + 8) S[nb][3] = -INFINITY;
            }
        }

        float mx0 = -INFINITY, mx1 = -INFINITY;
#pragma unroll
        for (int nb = 0; nb < 8; nb++) {
            mx0 = fmaxf(mx0, fmaxf(S[nb][0], S[nb][1]));
            mx1 = fmaxf(mx1, fmaxf(S[nb][2], S[nb][3]));
        }
        mx0 = fmaxf(mx0, __shfl_xor_sync(0xffffffffu, mx0, 1));
        mx0 = fmaxf(mx0, __shfl_xor_sync(0xffffffffu, mx0, 2));
        mx1 = fmaxf(mx1, __shfl_xor_sync(0xffffffffu, mx1, 1));
        mx1 = fmaxf(mx1, __shfl_xor_sync(0xffffffffu, mx1, 2));
        float newm0 = fmaxf(mr[0], mx0);
        float newm1 = fmaxf(mr[1], mx1);
        float a0 = exp2f((mr[0] - newm0) * LOG2E);
        float a1 = exp2f((mr[1] - newm1) * LOG2E);
        mr[0] = newm0; mr[1] = newm1;

        float sum0 = 0.f, sum1 = 0.f;
#pragma unroll
        for (int nb = 0; nb < 8; nb++) {
            S[nb][0] = exp2f((S[nb][0] - newm0) * LOG2E);
            S[nb][1] = exp2f((S[nb][1] - newm0) * LOG2E);
            S[nb][2] = exp2f((S[nb][2] - newm1) * LOG2E);
            S[nb][3] = exp2f((S[nb][3] - newm1) * LOG2E);
            sum0 += S[nb][0] + S[nb][1];
            sum1 += S[nb][2] + S[nb][3];
        }
        sum0 += __shfl_xor_sync(0xffffffffu, sum0, 1);
        sum0 += __shfl_xor_sync(0xffffffffu, sum0, 2);
        sum1 += __shfl_xor_sync(0xffffffffu, sum1, 1);
        sum1 += __shfl_xor_sync(0xffffffffu, sum1, 2);
        lr[0] = lr[0] * a0 + sum0;
        lr[1] = lr[1] * a1 + sum1;

        uint32_t ph[4][4], pl[4][4];
#pragma unroll
        for (int c = 0; c < 4; c++) {
            int nA = 2 * c, nB = 2 * c + 1;
            split2(S[nA][0], S[nA][1], ph[c][0], pl[c][0]);
            split2(S[nA][2], S[nA][3], ph[c][1], pl[c][1]);
            split2(S[nB][0], S[nB][1], ph[c][2], pl[c][2]);
            split2(S[nB][2], S[nB][3], ph[c][3], pl[c][3]);
        }

#pragma unroll
        for (int db = 0; db < 8; db++) {
            D[db][0] *= a0; D[db][1] *= a0;
            D[db][2] *= a1; D[db][3] *= a1;
        }

#pragma unroll
        for (int c = 0; c < 4; c++) {
#pragma unroll
            for (int dbp = 0; dbp < 4; dbp++) {
                uint32_t vh[4], vl[4];
                uint32_t off = (uint32_t)((c * 16 + vb_row) * KPAD + dbp * 16 + vb_col) * 2;
                ldm_x4_t(vh, bVh + off);
                ldm_x4_t(vl, bVl + off);
                mma_bf16(D[2 * dbp],     ph[c], vh);
                mma_bf16(D[2 * dbp],     ph[c], vl);
                mma_bf16(D[2 * dbp],     pl[c], vh);
                mma_bf16(D[2 * dbp + 1], ph[c], vh + 2);
                mma_bf16(D[2 * dbp + 1], ph[c], vl + 2);
                mma_bf16(D[2 * dbp + 1], pl[c], vh + 2);
            }
        }
        __syncthreads();
    }

    // ---- epilogue: normalize + bf16 split to g_aoh/g_aol ----
    float inv0 = 1.0f / lr[0];
    float inv1 = 1.0f / lr[1];
    int row0 = qt * 64 + wid * 16 + g;
#pragma unroll
    for (int db = 0; db < 8; db++) {
        int col = h * HD + db * 8 + 2 * t;
        uint32_t h0, l0, h1, l1;
        split2(D[db][0] * inv0, D[db][1] * inv0, h0, l0);
        split2(D[db][2] * inv1, D[db][3] * inv1, h1, l1);
        *reinterpret_cast<uint32_t*>(g_aoh + (size_t)row0 * DIM + col) = h0;
        *reinterpret_cast<uint32_t*>(g_aol + (size_t)row0 * DIM + col) = l0;
        *reinterpret_cast<uint32_t*>(g_aoh + (size_t)(row0 + 8) * DIM + col) = h1;
        *reinterpret_cast<uint32_t*>(g_aol + (size_t)(row0 + 8) * DIM + col) = l1;
    }
}

// ---------------------------------------------------------------------------
// Launch
// ---------------------------------------------------------------------------
extern "C" void kernel_launch(void* const* d_in, const int* in_sizes, int n_in,
                              void* d_out, int out_size) {
    const float* x  = (const float*)d_in[0];
    const float* wq = (const float*)d_in[1];
    const float* wk = (const float*)d_in[2];
    const float* wv = (const float*)d_in[3];
    const float* wo = (const float*)d_in[4];
    float* out = (float*)d_out;

    float* q = nullptr;  cudaGetSymbolAddress((void**)&q, g_q);
    float* k = nullptr;  cudaGetSymbolAddress((void**)&k, g_k);
    uint16_t *xh, *xl, *wqh, *wql, *wkh, *wkl, *wvh, *wvl, *woh, *wol;
    uint16_t *vh, *vl, *aoh, *aol;
    cudaGetSymbolAddress((void**)&xh, g_xh);   cudaGetSymbolAddress((void**)&xl, g_xl);
    cudaGetSymbolAddress((void**)&wqh, g_wqh); cudaGetSymbolAddress((void**)&wql, g_wql);
    cudaGetSymbolAddress((void**)&wkh, g_wkh); cudaGetSymbolAddress((void**)&wkl, g_wkl);
    cudaGetSymbolAddress((void**)&wvh, g_wvh); cudaGetSymbolAddress((void**)&wvl, g_wvl);
    cudaGetSymbolAddress((void**)&woh, g_woh); cudaGetSymbolAddress((void**)&wol, g_wol);
    cudaGetSymbolAddress((void**)&vh, g_vh);   cudaGetSymbolAddress((void**)&vl, g_vl);
    cudaGetSymbolAddress((void**)&aoh, g_aoh); cudaGetSymbolAddress((void**)&aol, g_aol);

    const int gemm_smem = 8 * GSZ * (int)sizeof(uint16_t);   // 81920
    static bool configured = false;
    if (!configured) {
        cudaFuncSetAttribute(mma_gemm_bf16,
                             cudaFuncAttributeMaxDynamicSharedMemorySize, gemm_smem);
        configured = true;
    }

    // 1) split inputs to bf16 hi/lo
    conv_split<<<(S_LEN * DIM / 4 + 255) / 256, 256>>>(
        (const float4*)x, (uint2*)xh, (uint2*)xl, S_LEN * DIM / 4);
    conv_split<<<(DIM * DIM / 4 + 255) / 256, 256>>>(
        (const float4*)wq, (uint2*)wqh, (uint2*)wql, DIM * DIM / 4);
    conv_split<<<(KVDIM * DIM / 4 + 255) / 256, 256>>>(
        (const float4*)wk, (uint2*)wkh, (uint2*)wkl, KVDIM * DIM / 4);
    conv_split<<<(KVDIM * DIM / 4 + 255) / 256, 256>>>(
        (const float4*)wv, (uint2*)wvh, (uint2*)wvl, KVDIM * DIM / 4);
    conv_split<<<(DIM * DIM / 4 + 255) / 256, 256>>>(
        (const float4*)wo, (uint2*)woh, (uint2*)wol, DIM * DIM / 4);

    // 2) projections
    mma_gemm_bf16<<<dim3(DIM / 128, S_LEN / 128), 256, gemm_smem>>>(
        xh, xl, wqh, wql, q, nullptr, nullptr, S_LEN, DIM, DIM);
    mma_gemm_bf16<<<dim3(KVDIM / 128, S_LEN / 128), 256, gemm_smem>>>(
        xh, xl, wkh, wkl, k, nullptr, nullptr, S_LEN, KVDIM, DIM);
    mma_gemm_bf16<<<dim3(KVDIM / 128, S_LEN / 128), 256, gemm_smem>>>(
        xh, xl, wvh, wvl, nullptr, vh, vl, S_LEN, KVDIM, DIM);

    // 3) RoPE (+scale q) + split
    rope_table_kernel<<<S_LEN, 32>>>();
    rope_split_kernel<<<S_LEN, 256>>>();

    // 4) tensor-core flash attention
    attn_tc_kernel<<<dim3(S_LEN / 64, NH), 128>>>();

    // 5) output projection
    mma_gemm_bf16<<<dim3(DIM / 128, S_LEN / 128), 256, gemm_smem>>>(
        aoh, aol, woh, wol, out, nullptr, nullptr, S_LEN, DIM, DIM);
}

// round 10
// speedup vs baseline: 1.2190x; 1.2190x over previous
#include <cuda_runtime.h>
#include <cuda_bf16.h>
#include <math.h>
#include <stdint.h>

#define S_LEN 2048
#define DIM 2048
#define NH 32
#define NKV 8
#define HD 64
#define KVDIM (NKV * HD)   // 512

// ---------------------------------------------------------------------------
// Scratch (bf16 hi/lo pairs stored as uint16)
// ---------------------------------------------------------------------------
__device__ __align__(16) uint16_t g_xh[S_LEN * DIM],  g_xl[S_LEN * DIM];
__device__ __align__(16) uint16_t g_wqh[DIM * DIM],   g_wql[DIM * DIM];
__device__ __align__(16) uint16_t g_wkh[KVDIM * DIM], g_wkl[KVDIM * DIM];
__device__ __align__(16) uint16_t g_wvh[KVDIM * DIM], g_wvl[KVDIM * DIM];
__device__ __align__(16) uint16_t g_woh[DIM * DIM],   g_wol[DIM * DIM];
__device__ __align__(16) uint16_t g_qh[S_LEN * DIM],  g_ql[S_LEN * DIM];
__device__ __align__(16) uint16_t g_kh[S_LEN * KVDIM], g_kl[S_LEN * KVDIM];
__device__ __align__(16) uint16_t g_vh[S_LEN * KVDIM], g_vl[S_LEN * KVDIM];
__device__ __align__(16) uint16_t g_aoh[S_LEN * DIM], g_aol[S_LEN * DIM];
__device__ float g_ct[S_LEN * 32];
__device__ float g_st[S_LEN * 32];

// ---------------------------------------------------------------------------
// helpers
// ---------------------------------------------------------------------------
__device__ __forceinline__ uint32_t smem_u32(const void* p) {
    uint32_t a;
    asm("{ .reg .u64 t; cvta.to.shared.u64 t, %1; cvt.u32.u64 %0, t; }"
        : "=r"(a) : "l"(p));
    return a;
}
__device__ __forceinline__ void ldm_x4(uint32_t* r, uint32_t addr) {
    asm volatile("ldmatrix.sync.aligned.m8n8.x4.shared.b16 {%0,%1,%2,%3}, [%4];"
                 : "=r"(r[0]), "=r"(r[1]), "=r"(r[2]), "=r"(r[3]) : "r"(addr));
}
__device__ __forceinline__ void ldm_x4_t(uint32_t* r, uint32_t addr) {
    asm volatile("ldmatrix.sync.aligned.m8n8.x4.trans.shared.b16 {%0,%1,%2,%3}, [%4];"
                 : "=r"(r[0]), "=r"(r[1]), "=r"(r[2]), "=r"(r[3]) : "r"(addr));
}
__device__ __forceinline__ void mma_bf16(float* d, const uint32_t* a,
                                         const uint32_t* b) {
    asm volatile(
        "mma.sync.aligned.m16n8k16.row.col.f32.bf16.bf16.f32 "
        "{%0,%1,%2,%3}, {%4,%5,%6,%7}, {%8,%9}, {%0,%1,%2,%3};"
        : "+f"(d[0]), "+f"(d[1]), "+f"(d[2]), "+f"(d[3])
        : "r"(a[0]), "r"(a[1]), "r"(a[2]), "r"(a[3]), "r"(b[0]), "r"(b[1]));
}
__device__ __forceinline__ void split2(float x, float y, uint32_t& hi, uint32_t& lo) {
    __nv_bfloat162 h = __float22bfloat162_rn(make_float2(x, y));
    hi = *reinterpret_cast<uint32_t*>(&h);
    __nv_bfloat162 l = __float22bfloat162_rn(make_float2(
        x - __bfloat162float(h.x), y - __bfloat162float(h.y)));
    lo = *reinterpret_cast<uint32_t*>(&l);
}

#define CP_ASYNC16(dst_u32, gsrc) \
    asm volatile("cp.async.cg.shared.global [%0], [%1], 16;" \
                 :: "r"(dst_u32), "l"(gsrc) : "memory")
#define CP_COMMIT() asm volatile("cp.async.commit_group;" ::: "memory")
#define CP_WAIT(n)  asm volatile("cp.async.wait_group %0;" :: "n"(n) : "memory")

// ---------------------------------------------------------------------------
// Fused fp32 -> bf16 hi/lo split for all five inputs (one launch)
// ---------------------------------------------------------------------------
#define N4_X  (S_LEN * DIM / 4)
#define N4_WQ (DIM * DIM / 4)
#define N4_WK (KVDIM * DIM / 4)
#define N4_WV (KVDIM * DIM / 4)
#define N4_WO (DIM * DIM / 4)
#define C1 (N4_X)
#define C2 (C1 + N4_WQ)
#define C3 (C2 + N4_WK)
#define C4 (C3 + N4_WV)
#define C5 (C4 + N4_WO)

__global__ __launch_bounds__(256)
void conv_split_all(const float4* __restrict__ x, const float4* __restrict__ wq,
                    const float4* __restrict__ wk, const float4* __restrict__ wv,
                    const float4* __restrict__ wo) {
    int i = blockIdx.x * 256 + threadIdx.x;
    if (i >= C5) return;
    const float4* src;
    uint2 *dh, *dl;
    int j;
    if (i < C1)      { src = x;  dh = (uint2*)g_xh;  dl = (uint2*)g_xl;  j = i; }
    else if (i < C2) { src = wq; dh = (uint2*)g_wqh; dl = (uint2*)g_wql; j = i - C1; }
    else if (i < C3) { src = wk; dh = (uint2*)g_wkh; dl = (uint2*)g_wkl; j = i - C2; }
    else if (i < C4) { src = wv; dh = (uint2*)g_wvh; dl = (uint2*)g_wvl; j = i - C3; }
    else             { src = wo; dh = (uint2*)g_woh; dl = (uint2*)g_wol; j = i - C4; }
    float4 f = src[j];
    uint2 h, l;
    split2(f.x, f.y, h.x, l.x);
    split2(f.z, f.w, h.y, l.y);
    dh[j] = h;
    dl[j] = l;
}

// ---------------------------------------------------------------------------
// RoPE cos/sin table (verified: fp32 angle, high-precision trig)
// ---------------------------------------------------------------------------
__global__ void rope_table_kernel() {
    int s = blockIdx.x;
    int i = threadIdx.x;
    float e = (float)i / 32.0f;
    float fr = 1.0f / powf(10000.0f, e);
    float angf = (float)s * fr;
    double ang = (double)angf;
    g_ct[s * 32 + i] = (float)cos(ang);
    g_st[s * 32 + i] = (float)sin(ang);
}

// ---------------------------------------------------------------------------
// Fused QKV GEMM (bf16x3, cp.async, one sync per chunk) with fused
// RoPE+scale+split epilogue. Grid (24, 16): n-tiles 0-15 -> Q, 16-19 -> K,
// 20-23 -> V. CTA 128x128, BK=32, 256 threads (8 warps 4x2).
// ---------------------------------------------------------------------------
#define GPAD 40
#define GSZ (128 * GPAD)

__global__ __launch_bounds__(256)
void qkv_gemm() {
    extern __shared__ uint16_t dsm[];
    const uint32_t sb = smem_u32(dsm);

    const int tid  = threadIdx.x;
    const int wid  = tid >> 5;
    const int lane = tid & 31;
    const int wm = (wid & 3) * 32;
    const int wn = (wid >> 2) * 64;
    const int m0 = blockIdx.y * 128;
    const int n0 = blockIdx.x * 128;

    // segment select
    const uint16_t *Bh, *Bl;
    int bn0, seg;
    if (n0 < 2048)      { Bh = g_wqh; Bl = g_wql; bn0 = n0;        seg = 0; }
    else if (n0 < 2560) { Bh = g_wkh; Bl = g_wkl; bn0 = n0 - 2048; seg = 1; }
    else                { Bh = g_wvh; Bl = g_wvl; bn0 = n0 - 2560; seg = 2; }

    float acc[2][8][4];
#pragma unroll
    for (int i = 0; i < 2; i++)
#pragma unroll
        for (int j = 0; j < 8; j++)
#pragma unroll
            for (int e = 0; e < 4; e++) acc[i][j][e] = 0.f;

    const int a_r = lane & 15;
    const int a_c = (lane >> 4) << 3;
    const int b_r = (lane & 7) + ((lane >> 4) << 3);
    const int b_c = ((lane >> 3) & 1) << 3;

    auto load_chunk = [&](int k0, int stage) {
#pragma unroll
        for (int i = 0; i < 2; i++) {
            int cid = tid + i * 256;
            int r = cid >> 2;
            int c = (cid & 3) * 8;
            uint32_t soff = (uint32_t)(r * GPAD + c) * 2;
            CP_ASYNC16(sb + (uint32_t)(0 + stage) * GSZ * 2 + soff,
                       g_xh + (size_t)(m0 + r) * DIM + k0 + c);
            CP_ASYNC16(sb + (uint32_t)(2 + stage) * GSZ * 2 + soff,
                       g_xl + (size_t)(m0 + r) * DIM + k0 + c);
            CP_ASYNC16(sb + (uint32_t)(4 + stage) * GSZ * 2 + soff,
                       Bh + (size_t)(bn0 + r) * DIM + k0 + c);
            CP_ASYNC16(sb + (uint32_t)(6 + stage) * GSZ * 2 + soff,
                       Bl + (size_t)(bn0 + r) * DIM + k0 + c);
        }
    };

    load_chunk(0, 0);
    CP_COMMIT();

    for (int ck = 0; ck < 64; ck++) {
        const int cur = ck & 1;
        CP_WAIT(0);
        __syncthreads();
        if (ck + 1 < 64) {
            load_chunk((ck + 1) * 32, (ck + 1) & 1);
            CP_COMMIT();
        }

        const uint32_t bAh = sb + (uint32_t)(0 + cur) * GSZ * 2;
        const uint32_t bAl = sb + (uint32_t)(2 + cur) * GSZ * 2;
        const uint32_t bBh = sb + (uint32_t)(4 + cur) * GSZ * 2;
        const uint32_t bBl = sb + (uint32_t)(6 + cur) * GSZ * 2;

#pragma unroll
        for (int ks = 0; ks < 2; ks++) {
            const int kc = ks * 16;
            uint32_t ah[2][4], al[2][4];
#pragma unroll
            for (int mi = 0; mi < 2; mi++) {
                uint32_t off = (uint32_t)((wm + mi * 16 + a_r) * GPAD + kc + a_c) * 2;
                ldm_x4(ah[mi], bAh + off);
                ldm_x4(al[mi], bAl + off);
            }
            uint32_t bh[8][2], bl[8][2];
#pragma unroll
            for (int nj = 0; nj < 4; nj++) {
                uint32_t off = (uint32_t)((wn + nj * 16 + b_r) * GPAD + kc + b_c) * 2;
                uint32_t t[4];
                ldm_x4(t, bBh + off);
                bh[nj * 2][0] = t[0]; bh[nj * 2][1] = t[1];
                bh[nj * 2 + 1][0] = t[2]; bh[nj * 2 + 1][1] = t[3];
                ldm_x4(t, bBl + off);
                bl[nj * 2][0] = t[0]; bl[nj * 2][1] = t[1];
                bl[nj * 2 + 1][0] = t[2]; bl[nj * 2 + 1][1] = t[3];
            }
#pragma unroll
            for (int mi = 0; mi < 2; mi++)
#pragma unroll
                for (int ni = 0; ni < 8; ni++) {
                    mma_bf16(acc[mi][ni], ah[mi], bh[ni]);
                    mma_bf16(acc[mi][ni], ah[mi], bl[ni]);
                    mma_bf16(acc[mi][ni], al[mi], bh[ni]);
                }
        }
    }

    // ---- epilogue ----
    const int g2 = lane >> 2, t2 = lane & 3;
    if (seg < 2) {
        // RoPE + (scale for q) + bf16 split. Thread holds both halves of
        // every rope pair: cols jj (ni) and jj+32 (ni+4).
        const int W = (seg == 0) ? DIM : KVDIM;
        uint16_t* dsth = (seg == 0) ? g_qh : g_kh;
        uint16_t* dstl = (seg == 0) ? g_ql : g_kl;
        const float scale = (seg == 0) ? 0.125f : 1.0f;
        const int cb = bn0 + wn;
#pragma unroll
        for (int mi = 0; mi < 2; mi++) {
            int r0 = m0 + wm + mi * 16 + g2;
#pragma unroll
            for (int ni = 0; ni < 4; ni++) {
                int jj = ni * 8 + 2 * t2;
                float2 c0 = *reinterpret_cast<const float2*>(g_ct + r0 * 32 + jj);
                float2 s0 = *reinterpret_cast<const float2*>(g_st + r0 * 32 + jj);
                float2 c1 = *reinterpret_cast<const float2*>(g_ct + (r0 + 8) * 32 + jj);
                float2 s1 = *reinterpret_cast<const float2*>(g_st + (r0 + 8) * 32 + jj);
                uint32_t h, l;
                // row r0
                float x1a = acc[mi][ni][0],     x1b = acc[mi][ni][1];
                float x2a = acc[mi][ni + 4][0], x2b = acc[mi][ni + 4][1];
                split2((x1a * c0.x - x2a * s0.x) * scale,
                       (x1b * c0.y - x2b * s0.y) * scale, h, l);
                *reinterpret_cast<uint32_t*>(dsth + (size_t)r0 * W + cb + jj) = h;
                *reinterpret_cast<uint32_t*>(dstl + (size_t)r0 * W + cb + jj) = l;
                split2((x2a * c0.x + x1a * s0.x) * scale,
                       (x2b * c0.y + x1b * s0.y) * scale, h, l);
                *reinterpret_cast<uint32_t*>(dsth + (size_t)r0 * W + cb + jj + 32) = h;
                *reinterpret_cast<uint32_t*>(dstl + (size_t)r0 * W + cb + jj + 32) = l;
                // row r0+8
                x1a = acc[mi][ni][2];     x1b = acc[mi][ni][3];
                x2a = acc[mi][ni + 4][2]; x2b = acc[mi][ni + 4][3];
                split2((x1a * c1.x - x2a * s1.x) * scale,
                       (x1b * c1.y - x2b * s1.y) * scale, h, l);
                *reinterpret_cast<uint32_t*>(dsth + (size_t)(r0 + 8) * W + cb + jj) = h;
                *reinterpret_cast<uint32_t*>(dstl + (size_t)(r0 + 8) * W + cb + jj) = l;
                split2((x2a * c1.x + x1a * s1.x) * scale,
                       (x2b * c1.y + x1b * s1.y) * scale, h, l);
                *reinterpret_cast<uint32_t*>(dsth + (size_t)(r0 + 8) * W + cb + jj + 32) = h;
                *reinterpret_cast<uint32_t*>(dstl + (size_t)(r0 + 8) * W + cb + jj + 32) = l;
            }
        }
    } else {
        // V: straight bf16 split
        const int cb = bn0 + wn;
#pragma unroll
        for (int mi = 0; mi < 2; mi++) {
            int r0 = m0 + wm + mi * 16 + g2;
#pragma unroll
            for (int ni = 0; ni < 8; ni++) {
                int cc = cb + ni * 8 + 2 * t2;
                uint32_t h, l;
                split2(acc[mi][ni][0], acc[mi][ni][1], h, l);
                *reinterpret_cast<uint32_t*>(g_vh + (size_t)r0 * KVDIM + cc) = h;
                *reinterpret_cast<uint32_t*>(g_vl + (size_t)r0 * KVDIM + cc) = l;
                split2(acc[mi][ni][2], acc[mi][ni][3], h, l);
                *reinterpret_cast<uint32_t*>(g_vh + (size_t)(r0 + 8) * KVDIM + cc) = h;
                *reinterpret_cast<uint32_t*>(g_vl + (size_t)(r0 + 8) * KVDIM + cc) = l;
            }
        }
    }
}

// ---------------------------------------------------------------------------
// O projection GEMM: out[M,N] = ao @ wo^T, bf16x3, fp32 output.
// ---------------------------------------------------------------------------
__global__ __launch_bounds__(256)
void o_gemm(float* __restrict__ C) {
    extern __shared__ uint16_t dsm[];
    const uint32_t sb = smem_u32(dsm);

    const int tid  = threadIdx.x;
    const int wid  = tid >> 5;
    const int lane = tid & 31;
    const int wm = (wid & 3) * 32;
    const int wn = (wid >> 2) * 64;
    const int m0 = blockIdx.y * 128;
    const int n0 = blockIdx.x * 128;

    float acc[2][8][4];
#pragma unroll
    for (int i = 0; i < 2; i++)
#pragma unroll
        for (int j = 0; j < 8; j++)
#pragma unroll
            for (int e = 0; e < 4; e++) acc[i][j][e] = 0.f;

    const int a_r = lane & 15;
    const int a_c = (lane >> 4) << 3;
    const int b_r = (lane & 7) + ((lane >> 4) << 3);
    const int b_c = ((lane >> 3) & 1) << 3;

    auto load_chunk = [&](int k0, int stage) {
#pragma unroll
        for (int i = 0; i < 2; i++) {
            int cid = tid + i * 256;
            int r = cid >> 2;
            int c = (cid & 3) * 8;
            uint32_t soff = (uint32_t)(r * GPAD + c) * 2;
            CP_ASYNC16(sb + (uint32_t)(0 + stage) * GSZ * 2 + soff,
                       g_aoh + (size_t)(m0 + r) * DIM + k0 + c);
            CP_ASYNC16(sb + (uint32_t)(2 + stage) * GSZ * 2 + soff,
                       g_aol + (size_t)(m0 + r) * DIM + k0 + c);
            CP_ASYNC16(sb + (uint32_t)(4 + stage) * GSZ * 2 + soff,
                       g_woh + (size_t)(n0 + r) * DIM + k0 + c);
            CP_ASYNC16(sb + (uint32_t)(6 + stage) * GSZ * 2 + soff,
                       g_wol + (size_t)(n0 + r) * DIM + k0 + c);
        }
    };

    load_chunk(0, 0);
    CP_COMMIT();

    for (int ck = 0; ck < 64; ck++) {
        const int cur = ck & 1;
        CP_WAIT(0);
        __syncthreads();
        if (ck + 1 < 64) {
            load_chunk((ck + 1) * 32, (ck + 1) & 1);
            CP_COMMIT();
        }

        const uint32_t bAh = sb + (uint32_t)(0 + cur) * GSZ * 2;
        const uint32_t bAl = sb + (uint32_t)(2 + cur) * GSZ * 2;
        const uint32_t bBh = sb + (uint32_t)(4 + cur) * GSZ * 2;
        const uint32_t bBl = sb + (uint32_t)(6 + cur) * GSZ * 2;

#pragma unroll
        for (int ks = 0; ks < 2; ks++) {
            const int kc = ks * 16;
            uint32_t ah[2][4], al[2][4];
#pragma unroll
            for (int mi = 0; mi < 2; mi++) {
                uint32_t off = (uint32_t)((wm + mi * 16 + a_r) * GPAD + kc + a_c) * 2;
                ldm_x4(ah[mi], bAh + off);
                ldm_x4(al[mi], bAl + off);
            }
            uint32_t bh[8][2], bl[8][2];
#pragma unroll
            for (int nj = 0; nj < 4; nj++) {
                uint32_t off = (uint32_t)((wn + nj * 16 + b_r) * GPAD + kc + b_c) * 2;
                uint32_t t[4];
                ldm_x4(t, bBh + off);
                bh[nj * 2][0] = t[0]; bh[nj * 2][1] = t[1];
                bh[nj * 2 + 1][0] = t[2]; bh[nj * 2 + 1][1] = t[3];
                ldm_x4(t, bBl + off);
                bl[nj * 2][0] = t[0]; bl[nj * 2][1] = t[1];
                bl[nj * 2 + 1][0] = t[2]; bl[nj * 2 + 1][1] = t[3];
            }
#pragma unroll
            for (int mi = 0; mi < 2; mi++)
#pragma unroll
                for (int ni = 0; ni < 8; ni++) {
                    mma_bf16(acc[mi][ni], ah[mi], bh[ni]);
                    mma_bf16(acc[mi][ni], ah[mi], bl[ni]);
                    mma_bf16(acc[mi][ni], al[mi], bh[ni]);
                }
        }
    }

    const int g2 = lane >> 2, t2 = lane & 3;
#pragma unroll
    for (int mi = 0; mi < 2; mi++) {
        int r0 = m0 + wm + mi * 16 + g2;
#pragma unroll
        for (int ni = 0; ni < 8; ni++) {
            int c = n0 + wn + ni * 8 + t2 * 2;
            *reinterpret_cast<float2*>(C + (size_t)r0 * DIM + c) =
                make_float2(acc[mi][ni][0], acc[mi][ni][1]);
            *reinterpret_cast<float2*>(C + (size_t)(r0 + 8) * DIM + c) =
                make_float2(acc[mi][ni][2], acc[mi][ni][3]);
        }
    }
}

// ---------------------------------------------------------------------------
// Tensor-core flash attention (unchanged from R9 — passing)
// ---------------------------------------------------------------------------
#define KPAD 72
#define LOG2E 1.4426950408889634f

__global__ __launch_bounds__(128)
void attn_tc_kernel() {
    __shared__ __align__(16) uint16_t sKh[64][KPAD];
    __shared__ __align__(16) uint16_t sKl[64][KPAD];
    __shared__ __align__(16) uint16_t sVh[64][KPAD];
    __shared__ __align__(16) uint16_t sVl[64][KPAD];

    const int qt = (int)gridDim.x - 1 - (int)blockIdx.x;
    const int h  = blockIdx.y;
    const int kvh = h >> 2;
    const int tid = threadIdx.x;
    const int wid = tid >> 5;
    const int lane = tid & 31;
    const int g = lane >> 2;
    const int t = lane & 3;

    const uint32_t bKh = smem_u32(sKh), bKl = smem_u32(sKl);
    const uint32_t bVh = smem_u32(sVh), bVl = smem_u32(sVl);

#pragma unroll
    for (int it = 0; it < 4; it++) {
        int cid = tid + it * 128;
        int r = cid >> 3;
        int c = (cid & 7) * 8;
        *reinterpret_cast<uint4*>(&sKh[r][c]) = *reinterpret_cast<const uint4*>(
            g_qh + (size_t)(qt * 64 + r) * DIM + h * HD + c);
        *reinterpret_cast<uint4*>(&sKl[r][c]) = *reinterpret_cast<const uint4*>(
            g_ql + (size_t)(qt * 64 + r) * DIM + h * HD + c);
    }
    __syncthreads();

    uint32_t qh[4][4], ql[4][4];
    {
        int row = wid * 16 + (lane & 15);
        int col = ((lane >> 4) & 1) * 8;
#pragma unroll
        for (int c = 0; c < 4; c++) {
            uint32_t off = (uint32_t)(row * KPAD + c * 16 + col) * 2;
            ldm_x4(qh[c], bKh + off);
            ldm_x4(ql[c], bKl + off);
        }
    }
    __syncthreads();

    float mr[2] = {-INFINITY, -INFINITY};
    float lr[2] = {0.f, 0.f};
    float D[8][4];
#pragma unroll
    for (int i = 0; i < 8; i++)
#pragma unroll
        for (int j = 0; j < 4; j++) D[i][j] = 0.f;

    const int kb_row = (lane & 7) + ((lane >> 4) << 3);
    const int kb_col = ((lane >> 3) & 1) * 8;
    const int vb_row = (lane & 7) + (((lane >> 3) & 1) << 3);
    const int vb_col = ((lane >> 4) & 1) * 8;

    for (int kt = 0; kt <= qt; kt++) {
#pragma unroll
        for (int it = 0; it < 4; it++) {
            int cid = tid + it * 128;
            int r = cid >> 3;
            int c = (cid & 7) * 8;
            size_t off = (size_t)(kt * 64 + r) * KVDIM + kvh * HD + c;
            *reinterpret_cast<uint4*>(&sKh[r][c]) =
                *reinterpret_cast<const uint4*>(g_kh + off);
            *reinterpret_cast<uint4*>(&sKl[r][c]) =
                *reinterpret_cast<const uint4*>(g_kl + off);
            *reinterpret_cast<uint4*>(&sVh[r][c]) =
                *reinterpret_cast<const uint4*>(g_vh + off);
            *reinterpret_cast<uint4*>(&sVl[r][c]) =
                *reinterpret_cast<const uint4*>(g_vl + off);
        }
        __syncthreads();

        float S[8][4];
#pragma unroll
        for (int i = 0; i < 8; i++)
#pragma unroll
            for (int j = 0; j < 4; j++) S[i][j] = 0.f;

#pragma unroll
        for (int c = 0; c < 4; c++) {
#pragma unroll
            for (int nbp = 0; nbp < 4; nbp++) {
                uint32_t kh[4], kl[4];
                uint32_t off = (uint32_t)((nbp * 16 + kb_row) * KPAD + c * 16 + kb_col) * 2;
                ldm_x4(kh, bKh + off);
                ldm_x4(kl, bKl + off);
                mma_bf16(S[2 * nbp],     qh[c], kh);
                mma_bf16(S[2 * nbp],     qh[c], kl);
                mma_bf16(S[2 * nbp],     ql[c], kh);
                mma_bf16(S[2 * nbp + 1], qh[c], kh + 2);
                mma_bf16(S[2 * nbp + 1], qh[c], kl + 2);
                mma_bf16(S[2 * nbp + 1], ql[c], kh + 2);
            }
        }

        if (kt == qt) {
            int r0 = wid * 16 + g;
#pragma unroll
            for (int nb = 0; nb < 8; nb++) {
                int c0 = nb * 8 + 2 * t;
                if (c0 > r0)     S[nb][0] = -INFINITY;
                if (c0 + 1 > r0) S[nb][1] = -INFINITY;
                if (c0 > r0 + 8)     S[nb][2] = -INFINITY;
                if (c0 + 1 > r0 + 8) S[nb][3] = -INFINITY;
            }
        }

        float mx0 = -INFINITY, mx1 = -INFINITY;
#pragma unroll
        for (int nb = 0; nb < 8; nb++) {
            mx0 = fmaxf(mx0, fmaxf(S[nb][0], S[nb][1]));
            mx1 = fmaxf(mx1, fmaxf(S[nb][2], S[nb][3]));
        }
        mx0 = fmaxf(mx0, __shfl_xor_sync(0xffffffffu, mx0, 1));
        mx0 = fmaxf(mx0, __shfl_xor_sync(0xffffffffu, mx0, 2));
        mx1 = fmaxf(mx1, __shfl_xor_sync(0xffffffffu, mx1, 1));
        mx1 = fmaxf(mx1, __shfl_xor_sync(0xffffffffu, mx1, 2));
        float newm0 = fmaxf(mr[0], mx0);
        float newm1 = fmaxf(mr[1], mx1);
        float a0 = exp2f((mr[0] - newm0) * LOG2E);
        float a1 = exp2f((mr[1] - newm1) * LOG2E);
        mr[0] = newm0; mr[1] = newm1;

        float sum0 = 0.f, sum1 = 0.f;
#pragma unroll
        for (int nb = 0; nb < 8; nb++) {
            S[nb][0] = exp2f((S[nb][0] - newm0) * LOG2E);
            S[nb][1] = exp2f((S[nb][1] - newm0) * LOG2E);
            S[nb][2] = exp2f((S[nb][2] - newm1) * LOG2E);
            S[nb][3] = exp2f((S[nb][3] - newm1) * LOG2E);
            sum0 += S[nb][0] + S[nb][1];
            sum1 += S[nb][2] + S[nb][3];
        }
        sum0 += __shfl_xor_sync(0xffffffffu, sum0, 1);
        sum0 += __shfl_xor_sync(0xffffffffu, sum0, 2);
        sum1 += __shfl_xor_sync(0xffffffffu, sum1, 1);
        sum1 += __shfl_xor_sync(0xffffffffu, sum1, 2);
        lr[0] = lr[0] * a0 + sum0;
        lr[1] = lr[1] * a1 + sum1;

        uint32_t ph[4][4], pl[4][4];
#pragma unroll
        for (int c = 0; c < 4; c++) {
            int nA = 2 * c, nB = 2 * c + 1;
            split2(S[nA][0], S[nA][1], ph[c][0], pl[c][0]);
            split2(S[nA][2], S[nA][3], ph[c][1], pl[c][1]);
            split2(S[nB][0], S[nB][1], ph[c][2], pl[c][2]);
            split2(S[nB][2], S[nB][3], ph[c][3], pl[c][3]);
        }

#pragma unroll
        for (int db = 0; db < 8; db++) {
            D[db][0] *= a0; D[db][1] *= a0;
            D[db][2] *= a1; D[db][3] *= a1;
        }

#pragma unroll
        for (int c = 0; c < 4; c++) {
#pragma unroll
            for (int dbp = 0; dbp < 4; dbp++) {
                uint32_t vh[4], vl[4];
                uint32_t off = (uint32_t)((c * 16 + vb_row) * KPAD + dbp * 16 + vb_col) * 2;
                ldm_x4_t(vh, bVh + off);
                ldm_x4_t(vl, bVl + off);
                mma_bf16(D[2 * dbp],     ph[c], vh);
                mma_bf16(D[2 * dbp],     ph[c], vl);
                mma_bf16(D[2 * dbp],     pl[c], vh);
                mma_bf16(D[2 * dbp + 1], ph[c], vh + 2);
                mma_bf16(D[2 * dbp + 1], ph[c], vl + 2);
                mma_bf16(D[2 * dbp + 1], pl[c], vh + 2);
            }
        }
        __syncthreads();
    }

    float inv0 = 1.0f / lr[0];
    float inv1 = 1.0f / lr[1];
    int row0 = qt * 64 + wid * 16 + g;
#pragma unroll
    for (int db = 0; db < 8; db++) {
        int col = h * HD + db * 8 + 2 * t;
        uint32_t h0, l0, h1, l1;
        split2(D[db][0] * inv0, D[db][1] * inv0, h0, l0);
        split2(D[db][2] * inv1, D[db][3] * inv1, h1, l1);
        *reinterpret_cast<uint32_t*>(g_aoh + (size_t)row0 * DIM + col) = h0;
        *reinterpret_cast<uint32_t*>(g_aol + (size_t)row0 * DIM + col) = l0;
        *reinterpret_cast<uint32_t*>(g_aoh + (size_t)(row0 + 8) * DIM + col) = h1;
        *reinterpret_cast<uint32_t*>(g_aol + (size_t)(row0 + 8) * DIM + col) = l1;
    }
}

// ---------------------------------------------------------------------------
// Launch: rope_table -> conv_all -> qkv_gemm(+rope epi) -> attn -> o_gemm
// ---------------------------------------------------------------------------
extern "C" void kernel_launch(void* const* d_in, const int* in_sizes, int n_in,
                              void* d_out, int out_size) {
    const float* x  = (const float*)d_in[0];
    const float* wq = (const float*)d_in[1];
    const float* wk = (const float*)d_in[2];
    const float* wv = (const float*)d_in[3];
    const float* wo = (const float*)d_in[4];
    float* out = (float*)d_out;

    const int gemm_smem = 8 * GSZ * (int)sizeof(uint16_t);   // 81920
    static bool configured = false;
    if (!configured) {
        cudaFuncSetAttribute(qkv_gemm,
                             cudaFuncAttributeMaxDynamicSharedMemorySize, gemm_smem);
        cudaFuncSetAttribute(o_gemm,
                             cudaFuncAttributeMaxDynamicSharedMemorySize, gemm_smem);
        configured = true;
    }

    rope_table_kernel<<<S_LEN, 32>>>();
    conv_split_all<<<(C5 + 255) / 256, 256>>>(
        (const float4*)x, (const float4*)wq, (const float4*)wk,
        (const float4*)wv, (const float4*)wo);
    qkv_gemm<<<dim3(24, 16), 256, gemm_smem>>>();
    attn_tc_kernel<<<dim3(S_LEN / 64, NH), 128>>>();
    o_gemm<<<dim3(16, 16), 256, gemm_smem>>>(out);
}